// round 16
// baseline (speedup 1.0000x reference)
#include <cuda_runtime.h>
#include <cuda_fp16.h>
#include <cstdint>
#include <math.h>

#define Bn 8
#define C  256
#define N  4096

// ---------------- scratch ----------------
__device__ __half d_fp[Bn * N * 64];            // f packed fp16 [b][n][hi k0..31 | lo k0..31]
__device__ __half d_gp[Bn * N * 64];            // g packed
__device__ __half d_h [(size_t)Bn * C * N];     // H = h_w x + h_b, fp16 [b][c][j] (NOT Z-scaled)
__device__ __half d_wh[320 * 256];              // W = [fw;gw;hw] split hi
__device__ __half d_wl[320 * 256];              // W split lo
__device__ float d_rz[Bn * N];                  // 1/Z_j

// ---------------- helpers ----------------
__device__ __forceinline__ uint32_t smem_u32(const void* p) {
    uint32_t a;
    asm("{ .reg .u64 t; cvta.to.shared.u64 t, %1; cvt.u32.u64 %0, t; }" : "=r"(a) : "l"(p));
    return a;
}
__device__ __forceinline__ void ldsm4(uint32_t* r, uint32_t a) {
    asm volatile("ldmatrix.sync.aligned.m8n8.x4.shared.b16 {%0,%1,%2,%3}, [%4];"
        : "=r"(r[0]), "=r"(r[1]), "=r"(r[2]), "=r"(r[3]) : "r"(a));
}
__device__ __forceinline__ void mma_f16(float* d, const uint32_t* a, const uint32_t* b) {
    asm volatile("mma.sync.aligned.m16n8k16.row.col.f32.f16.f16.f32 "
        "{%0,%1,%2,%3}, {%4,%5,%6,%7}, {%8,%9}, {%0,%1,%2,%3};"
        : "+f"(d[0]), "+f"(d[1]), "+f"(d[2]), "+f"(d[3])
        : "r"(a[0]), "r"(a[1]), "r"(a[2]), "r"(a[3]), "r"(b[0]), "r"(b[1]));
}
__device__ __forceinline__ void split2h(float v, __half& h, __half& l) {
    h = __float2half_rn(v);
    l = __float2half_rn(v - __half2float(h));
}
__device__ __forceinline__ void cp16(uint32_t dst, const void* src) {
    asm volatile("cp.async.cg.shared.global [%0], [%1], 16;" :: "r"(dst), "l"(src));
}
#define CP_COMMIT() asm volatile("cp.async.commit_group;" ::: "memory")
#define CP_WAIT0()  asm volatile("cp.async.wait_group 0;" ::: "memory")
#define CP_WAIT1()  asm volatile("cp.async.wait_group 1;" ::: "memory")
#define BAR_GRP256(id) asm volatile("bar.sync %0, 256;" :: "r"(id) : "memory")

// ---------------- W pre-split: [fw;gw;hw] -> packed fp16 hi/lo ----------------
__global__ __launch_bounds__(512) void k_prep(const float* __restrict__ fw,
                                              const float* __restrict__ gw,
                                              const float* __restrict__ hw) {
    int idx = blockIdx.x * 512 + threadIdx.x;   // 81920
    int row = idx >> 8, cc = idx & 255;
    const float* wp = row < 32 ? fw + row * 256
                     : row < 64 ? gw + (row - 32) * 256
                                : hw + (row - 64) * 256;
    __half h, l;
    split2h(wp[cc], h, l);
    d_wh[idx] = h;
    d_wl[idx] = l;
}

// ---------------- merged projections via 3-term fp16 HMMA, W tiles via cp.async ----------------
// grid (32 nb, 8 b), 512 threads, dyn smem 71680
__global__ __launch_bounds__(512, 1) void k_proj(
    const float* __restrict__ x,
    const float* __restrict__ fb, const float* __restrict__ gb, const float* __restrict__ hb) {
    extern __shared__ char sm[];
    const int WH = 0, WL = 25600, XH = 51200, XL = 61440;
    uint32_t sb = smem_u32(sm);
    int tid = threadIdx.x, lane = tid & 31, w = tid >> 5;
    int nb = blockIdx.x, b = blockIdx.y;
    int wm = w & 3, wn = w >> 2;
    float ap[5][4][4] = {};

    for (int c0 = 0; c0 < 256; c0 += 32) {
        __syncthreads();
        for (int t = tid; t < 1280; t += 512) {
            int row = t >> 2, p = t & 3;
            cp16(sb + WH + row * 80 + p * 16, (const char*)d_wh + (row * 256 + c0 + p * 8) * 2);
            cp16(sb + WL + row * 80 + p * 16, (const char*)d_wl + (row * 256 + c0 + p * 8) * 2);
        }
        CP_COMMIT();
        for (int idx = tid; idx < 4096; idx += 512) {
            int cc = idx >> 7, n = idx & 127;
            __half h, l;
            split2h(x[((size_t)b * 256 + c0 + cc) * 4096 + nb * 128 + n], h, l);
            *(__half*)(sm + XH + n * 80 + cc * 2) = h;
            *(__half*)(sm + XL + n * 80 + cc * 2) = l;
        }
        CP_WAIT0();
        __syncthreads();
#pragma unroll
        for (int term = 0; term < 3; term++) {
            int Ab = term == 2 ? WL : WH;
            int Bb = term == 1 ? XL : XH;
#pragma unroll
            for (int k16 = 0; k16 < 2; k16++) {
                uint32_t af[5][4];
#pragma unroll
                for (int mi = 0; mi < 5; mi++)
                    ldsm4(af[mi], sb + Ab + (wm * 80 + mi * 16 + (lane & 15)) * 80 + k16 * 32 + (lane >> 4) * 16);
#pragma unroll
                for (int p = 0; p < 2; p++) {
                    uint32_t bq[4];
                    ldsm4(bq, sb + Bb + (wn * 32 + p * 16 + ((lane >> 4) & 1) * 8 + (lane & 7)) * 80
                              + k16 * 32 + ((lane >> 3) & 1) * 16);
#pragma unroll
                    for (int mi = 0; mi < 5; mi++) {
                        mma_f16(ap[mi][2 * p],     af[mi], bq);
                        mma_f16(ap[mi][2 * p + 1], af[mi], bq + 2);
                    }
                }
            }
        }
    }
#pragma unroll
    for (int mi = 0; mi < 5; mi++)
#pragma unroll
        for (int p = 0; p < 4; p++)
#pragma unroll
            for (int hf = 0; hf < 2; hf++) {
                int orow = wm * 80 + mi * 16 + hf * 8 + (lane >> 2);
                int n = nb * 128 + wn * 32 + p * 8 + 2 * (lane & 3);
                float v0 = ap[mi][p][hf * 2 + 0];
                float v1 = ap[mi][p][hf * 2 + 1];
                if (orow < 64) {
                    __half* o = orow < 32 ? d_fp : d_gp;
                    int oo = orow & 31;
                    float bz = orow < 32 ? fb[oo] : gb[oo];
                    __half h, l;
                    split2h(v0 + bz, h, l);
                    o[((size_t)b * N + n) * 64 + oo] = h;
                    o[((size_t)b * N + n) * 64 + 32 + oo] = l;
                    split2h(v1 + bz, h, l);
                    o[((size_t)b * N + n + 1) * 64 + oo] = h;
                    o[((size_t)b * N + n + 1) * 64 + 32 + oo] = l;
                } else {
                    int c = orow - 64;
                    float bz = hb[c];
                    __half2 hv = __floats2half2_rn(v0 + bz, v1 + bz);
                    *(__half2*)&d_h[((size_t)b * C + c) * N + n] = hv;
                }
            }
}

// ---------------- pass 1: Z_j via HMMA, 3-term, p-outer, g-frags hoisted, warp phase-skew ----------------
// grid (32 jb, 8 b), 256 threads, dyn smem 62464
__global__ __launch_bounds__(256, 1) void k_zsum() {
    extern __shared__ char sm[];
    const int SGH = 0, SGL = 10240;
    const int SFH[2] = {20480, 40960}, SFL[2] = {30720, 51200};
    const int SZ = 61440;
    uint32_t sb = smem_u32(sm);
    int tid = threadIdx.x, lane = tid & 31, w = tid >> 5;
    int jb = blockIdx.x, b = blockIdx.y;
    int wj = w & 3, wi2 = w >> 2;
    int ws = w >> 2;   // distinct per warp within an SMSP

    for (int t = tid; t < 1024; t += 256) {
        int row = t >> 3, p = t & 7;
        uint4 v = ((const uint4*)d_gp)[(size_t)(b * N + jb * 128 + row) * 8 + p];
        *(uint4*)(sm + (p < 4 ? SGH + row * 80 + p * 16 : SGL + row * 80 + (p - 4) * 16)) = v;
    }
    for (int t = tid; t < 1024; t += 256) {
        int row = t >> 3, p = t & 7;
        const char* src = (const char*)d_fp + ((size_t)(b * N + row) * 8 + p) * 16;
        cp16(sb + (p < 4 ? SFH[0] + row * 80 + p * 16 : SFL[0] + row * 80 + (p - 4) * 16), src);
    }
    CP_COMMIT();
    __syncthreads();

    uint32_t ga[2][2][2][4];
#pragma unroll
    for (int jt = 0; jt < 2; jt++)
#pragma unroll
        for (int k16 = 0; k16 < 2; k16++) {
            ldsm4(ga[jt][0][k16], sb + SGH + (wj * 32 + jt * 16 + (lane & 15)) * 80 + k16 * 32 + (lane >> 4) * 16);
            ldsm4(ga[jt][1][k16], sb + SGL + (wj * 32 + jt * 16 + (lane & 15)) * 80 + k16 * 32 + (lane >> 4) * 16);
        }

    float zacc[4] = {0.f, 0.f, 0.f, 0.f};
    for (int ibt = 0; ibt < 32; ibt++) {
        int cur = ibt & 1;
        __syncthreads();
        if (ibt < 31) {
            int nxt = 1 - cur;
            for (int t = tid; t < 1024; t += 256) {
                int row = t >> 3, p = t & 7;
                const char* src = (const char*)d_fp + ((size_t)(b * N + (ibt + 1) * 128 + row) * 8 + p) * 16;
                cp16(sb + (p < 4 ? SFH[nxt] + row * 80 + p * 16 : SFL[nxt] + row * 80 + (p - 4) * 16), src);
            }
        }
        CP_COMMIT();
        CP_WAIT1();
        __syncthreads();

#pragma unroll
        for (int pp = 0; pp < 4; pp++) {
            int p = (pp + ws) & 3;   // phase-skew
            float t0[4] = {}, t1[4] = {}, t2[4] = {}, t3[4] = {};
#pragma unroll
            for (int k16 = 0; k16 < 2; k16++) {
                uint32_t baddr = (wi2 * 64 + p * 16 + ((lane >> 4) & 1) * 8 + (lane & 7)) * 80
                                 + k16 * 32 + ((lane >> 3) & 1) * 16;
                uint32_t bh[4];
                ldsm4(bh, sb + SFH[cur] + baddr);
                mma_f16(t0, ga[0][0][k16], bh); mma_f16(t1, ga[0][0][k16], bh + 2);
                mma_f16(t2, ga[1][0][k16], bh); mma_f16(t3, ga[1][0][k16], bh + 2);
                mma_f16(t0, ga[0][1][k16], bh); mma_f16(t1, ga[0][1][k16], bh + 2);
                mma_f16(t2, ga[1][1][k16], bh); mma_f16(t3, ga[1][1][k16], bh + 2);
                uint32_t bl[4];
                ldsm4(bl, sb + SFL[cur] + baddr);
                mma_f16(t0, ga[0][0][k16], bl); mma_f16(t1, ga[0][0][k16], bl + 2);
                mma_f16(t2, ga[1][0][k16], bl); mma_f16(t3, ga[1][0][k16], bl + 2);
            }
            zacc[0] += __expf(t0[0]) + __expf(t0[1]) + __expf(t1[0]) + __expf(t1[1]);
            zacc[1] += __expf(t0[2]) + __expf(t0[3]) + __expf(t1[2]) + __expf(t1[3]);
            zacc[2] += __expf(t2[0]) + __expf(t2[1]) + __expf(t3[0]) + __expf(t3[1]);
            zacc[3] += __expf(t2[2]) + __expf(t2[3]) + __expf(t3[2]) + __expf(t3[3]);
        }
    }
#pragma unroll
    for (int m = 0; m < 4; m++) {
        float v = zacc[m];
        v += __shfl_xor_sync(0xffffffffu, v, 1);
        v += __shfl_xor_sync(0xffffffffu, v, 2);
        if ((lane & 3) == 0) {
            int jloc = wj * 32 + (m >> 1) * 16 + (m & 1) * 8 + (lane >> 2);
            *(float*)(sm + SZ + (wi2 * 128 + jloc) * 4) = v;
        }
    }
    __syncthreads();
    if (tid < 128) {
        float z = *(float*)(sm + SZ + tid * 4) + *(float*)(sm + SZ + (128 + tid) * 4);
        d_rz[b * N + jb * 128 + tid] = 1.f / z;
    }
}

// ---------------- pass 2: 512 threads, 2 groups x 8 warps; S -> exp -> E(group) -> O, phase-skewed ----------------
// grid (32 ib, 8 b), 512 threads, dyn smem 231424
__global__ __launch_bounds__(512, 1) void k_out(const float* __restrict__ x, float* __restrict__ out) {
    extern __shared__ char sm[];
    const int SFH = 0, SFL = 10240, SGH = 20480, SGL = 30720;
    const int SE = 40960;                       // E [128][272] group-local halves
    const int SHB[2] = {75776, 145408};         // 2 x H [256][272]
    const int SR = 215040;                      // rz for whole batch b: 16KB
    uint32_t sb = smem_u32(sm);
    int tid = threadIdx.x, lane = tid & 31, w = tid >> 5;
    int ib = blockIdx.x, b = blockIdx.y;
    int grp = w >> 3, wg = w & 7;
    int i0 = grp * 64 + (wg & 3) * 16;   // S phase: this warp's 16 i rows
    int jq = wg >> 2;                    // S phase: j half
    int ws = w >> 2;                     // distinct per warp within an SMSP

    // prologue: cp g(0), H(0), H(1); direct f + rz
    for (int t = tid; t < 1024; t += 512) {
        int row = t >> 3, p = t & 7;
        const char* src = (const char*)d_gp + ((size_t)(b * N + row) * 8 + p) * 16;
        cp16(sb + (p < 4 ? SGH + row * 80 + p * 16 : SGL + row * 80 + (p - 4) * 16), src);
    }
    CP_COMMIT();
    for (int t = tid; t < 4096; t += 512) {
        int row = t >> 4, u = t & 15;
        cp16(sb + SHB[0] + row * 272 + u * 16,
             (const char*)d_h + ((size_t)(b * C + row) * N + u * 8) * 2);
    }
    CP_COMMIT();
    for (int t = tid; t < 4096; t += 512) {
        int row = t >> 4, u = t & 15;
        cp16(sb + SHB[1] + row * 272 + u * 16,
             (const char*)d_h + ((size_t)(b * C + row) * N + 128 + u * 8) * 2);
    }
    CP_COMMIT();
    for (int t = tid; t < 1024; t += 512) {
        int row = t >> 3, p = t & 7;
        uint4 v = ((const uint4*)d_fp)[(size_t)(b * N + ib * 128 + row) * 8 + p];
        *(uint4*)(sm + (p < 4 ? SFH + row * 80 + p * 16 : SFL + row * 80 + (p - 4) * 16)) = v;
    }
    for (int t = tid; t < 1024; t += 512)
        ((float4*)(sm + SR))[t] = ((const float4*)(d_rz + (size_t)b * N))[t];
    __syncthreads();

    // hoist f A-frags (constant across all jb)
    uint32_t fah[2][4], fal[2][4];
#pragma unroll
    for (int k16 = 0; k16 < 2; k16++) {
        ldsm4(fah[k16], sb + SFH + (i0 + (lane & 15)) * 80 + k16 * 32 + (lane >> 4) * 16);
        ldsm4(fal[k16], sb + SFL + (i0 + (lane & 15)) * 80 + k16 * 32 + (lane >> 4) * 16);
    }

    float ao[2][8][4] = {};   // O: c = wg*32 + mi*16.., i = grp*64 + n*8..
    for (int jb = 0; jb < 32; jb++) {
        if (jb == 31) { CP_WAIT0(); } else { CP_WAIT1(); }  // tail: drain g(31) too
        __syncthreads();       // bar1: g/H visible, prev O done reading E

        // --- S (p-outer, 16i x 64j per warp, phase-skewed) with exp/pack/STS interleaved ---
        int irow = i0 + (lane >> 2);
#pragma unroll
        for (int pp = 0; pp < 4; pp++) {
            int p = (pp + ws) & 3;   // phase-skew
            float t0[4] = {}, t1[4] = {};
#pragma unroll
            for (int k16 = 0; k16 < 2; k16++) {
                uint32_t baddr = (jq * 64 + p * 16 + ((lane >> 4) & 1) * 8 + (lane & 7)) * 80
                                 + k16 * 32 + ((lane >> 3) & 1) * 16;
                uint32_t bh[4];
                ldsm4(bh, sb + SGH + baddr);
                mma_f16(t0, fah[k16], bh); mma_f16(t1, fah[k16], bh + 2);
                mma_f16(t0, fal[k16], bh); mma_f16(t1, fal[k16], bh + 2);
                uint32_t bl[4];
                ldsm4(bl, sb + SGL + baddr);
                mma_f16(t0, fah[k16], bl); mma_f16(t1, fah[k16], bl + 2);
            }
            int jc0 = jq * 64 + p * 16 + 2 * (lane & 3);
            float2 rz0 = *(float2*)(sm + SR + (jb * 128 + jc0) * 4);
            float2 rz1 = *(float2*)(sm + SR + (jb * 128 + jc0 + 8) * 4);
            __half2 h00 = __floats2half2_rn(__expf(t0[0]) * rz0.x, __expf(t0[1]) * rz0.y);
            __half2 h01 = __floats2half2_rn(__expf(t0[2]) * rz0.x, __expf(t0[3]) * rz0.y);
            __half2 h10 = __floats2half2_rn(__expf(t1[0]) * rz1.x, __expf(t1[1]) * rz1.y);
            __half2 h11 = __floats2half2_rn(__expf(t1[2]) * rz1.x, __expf(t1[3]) * rz1.y);
            *(uint32_t*)(sm + SE + irow * 272 + jc0 * 2)             = *(uint32_t*)&h00;
            *(uint32_t*)(sm + SE + (irow + 8) * 272 + jc0 * 2)       = *(uint32_t*)&h01;
            *(uint32_t*)(sm + SE + irow * 272 + (jc0 + 8) * 2)       = *(uint32_t*)&h10;
            *(uint32_t*)(sm + SE + (irow + 8) * 272 + (jc0 + 8) * 2) = *(uint32_t*)&h11;
        }
        BAR_GRP256(grp + 1);   // group-local (8 warps): our E half complete

        // --- O: A = H rows c (wg*32..+32), B = E rows i (grp*64..+64), k = j; phase-skewed ---
        int SH = SHB[jb & 1];
#pragma unroll
        for (int kk = 0; kk < 8; kk++) {
            int k16 = (kk + 2 * ws) & 7;   // phase-skew
            uint32_t af[2][4];
#pragma unroll
            for (int mi = 0; mi < 2; mi++)
                ldsm4(af[mi], sb + SH + (wg * 32 + mi * 16 + (lane & 15)) * 272 + k16 * 32 + (lane >> 4) * 16);
#pragma unroll
            for (int pp2 = 0; pp2 < 4; pp2++) {
                int p2 = (pp2 + ws) & 3;   // phase-skew
                uint32_t bq[4];
                ldsm4(bq, sb + SE + (grp * 64 + p2 * 16 + ((lane >> 4) & 1) * 8 + (lane & 7)) * 272
                          + k16 * 32 + ((lane >> 3) & 1) * 16);
#pragma unroll
                for (int mi = 0; mi < 2; mi++) {
                    mma_f16(ao[mi][2 * p2],     af[mi], bq);
                    mma_f16(ao[mi][2 * p2 + 1], af[mi], bq + 2);
                }
            }
        }
        __syncthreads();       // bar2: O reads of g/E/H(cur) done; buffers reusable

        if (jb < 31) {
            for (int t = tid; t < 1024; t += 512) {
                int row = t >> 3, p = t & 7;
                const char* src = (const char*)d_gp + ((size_t)(b * N + (jb + 1) * 128 + row) * 8 + p) * 16;
                cp16(sb + (p < 4 ? SGH + row * 80 + p * 16 : SGL + row * 80 + (p - 4) * 16), src);
            }
            CP_COMMIT();
        }
        if (jb < 30) {
            for (int t = tid; t < 4096; t += 512) {
                int row = t >> 4, u = t & 15;
                cp16(sb + SHB[jb & 1] + row * 272 + u * 16,
                     (const char*)d_h + ((size_t)(b * C + row) * N + (jb + 2) * 128 + u * 8) * 2);
            }
            CP_COMMIT();
        }
    }

    // epilogue: out[b][c][i] = O + x
#pragma unroll
    for (int mi = 0; mi < 2; mi++)
#pragma unroll
        for (int n = 0; n < 8; n++) {
            int c = wg * 32 + mi * 16 + (lane >> 2);
            int icol = ib * 128 + grp * 64 + n * 8 + 2 * (lane & 3);
            size_t idx = (size_t)(b * C + c) * N + icol;
            float2 xv = *(const float2*)&x[idx];
            *(float2*)&out[idx] = make_float2(ao[mi][n][0] + xv.x, ao[mi][n][1] + xv.y);
            idx += (size_t)8 * N;
            xv = *(const float2*)&x[idx];
            *(float2*)&out[idx] = make_float2(ao[mi][n][2] + xv.x, ao[mi][n][3] + xv.y);
        }
}

// ---------------- launch ----------------
extern "C" void kernel_launch(void* const* d_in, const int* in_sizes, int n_in,
                              void* d_out, int out_size) {
    const float* x  = (const float*)d_in[0];
    const float* fw = (const float*)d_in[1];
    const float* fb = (const float*)d_in[2];
    const float* gw = (const float*)d_in[3];
    const float* gb = (const float*)d_in[4];
    const float* hw = (const float*)d_in[5];
    const float* hb = (const float*)d_in[6];
    float* out = (float*)d_out;

    const int SM_P = 71680;
    const int SM_Z = 62464;
    const int SM_O = 231424;
    cudaFuncSetAttribute(k_proj, cudaFuncAttributeMaxDynamicSharedMemorySize, SM_P);
    cudaFuncSetAttribute(k_zsum, cudaFuncAttributeMaxDynamicSharedMemorySize, SM_Z);
    cudaFuncSetAttribute(k_out,  cudaFuncAttributeMaxDynamicSharedMemorySize, SM_O);

    k_prep<<<160, 512>>>(fw, gw, hw);
    k_proj<<<dim3(32, 8), 512, SM_P>>>(x, fb, gb, hb);
    k_zsum<<<dim3(32, 8), 256, SM_Z>>>();
    k_out<<<dim3(32, 8), 512, SM_O>>>(x, out);
}

// round 17
// speedup vs baseline: 3.7352x; 3.7352x over previous
#include <cuda_runtime.h>
#include <cuda_fp16.h>
#include <cstdint>
#include <math.h>

#define Bn 8
#define C  256
#define N  4096

// ---------------- scratch ----------------
__device__ __half d_fp[Bn * N * 64];            // f packed fp16 [b][n][hi k0..31 | lo k0..31]
__device__ __half d_gp[Bn * N * 64];            // g packed
__device__ __half d_h [(size_t)Bn * C * N];     // H = h_w x + h_b, fp16 [b][c][j] (NOT Z-scaled)
__device__ __half d_wh[320 * 256];              // W = [fw;gw;hw] split hi
__device__ __half d_wl[320 * 256];              // W split lo
__device__ float d_rz[Bn * N];                  // 1/Z_j

// ---------------- helpers ----------------
__device__ __forceinline__ uint32_t smem_u32(const void* p) {
    uint32_t a;
    asm("{ .reg .u64 t; cvta.to.shared.u64 t, %1; cvt.u32.u64 %0, t; }" : "=r"(a) : "l"(p));
    return a;
}
__device__ __forceinline__ void ldsm4(uint32_t* r, uint32_t a) {
    asm volatile("ldmatrix.sync.aligned.m8n8.x4.shared.b16 {%0,%1,%2,%3}, [%4];"
        : "=r"(r[0]), "=r"(r[1]), "=r"(r[2]), "=r"(r[3]) : "r"(a));
}
__device__ __forceinline__ void mma_f16(float* d, const uint32_t* a, const uint32_t* b) {
    asm volatile("mma.sync.aligned.m16n8k16.row.col.f32.f16.f16.f32 "
        "{%0,%1,%2,%3}, {%4,%5,%6,%7}, {%8,%9}, {%0,%1,%2,%3};"
        : "+f"(d[0]), "+f"(d[1]), "+f"(d[2]), "+f"(d[3])
        : "r"(a[0]), "r"(a[1]), "r"(a[2]), "r"(a[3]), "r"(b[0]), "r"(b[1]));
}
__device__ __forceinline__ void split2h(float v, __half& h, __half& l) {
    h = __float2half_rn(v);
    l = __float2half_rn(v - __half2float(h));
}
__device__ __forceinline__ void cp16(uint32_t dst, const void* src) {
    asm volatile("cp.async.cg.shared.global [%0], [%1], 16;" :: "r"(dst), "l"(src));
}
#define CP_COMMIT() asm volatile("cp.async.commit_group;" ::: "memory")
#define CP_WAIT0()  asm volatile("cp.async.wait_group 0;" ::: "memory")
#define CP_WAIT1()  asm volatile("cp.async.wait_group 1;" ::: "memory")
#define BAR_GRP256(id) asm volatile("bar.sync %0, 256;" :: "r"(id) : "memory")

// ---------------- W pre-split: [fw;gw;hw] -> packed fp16 hi/lo ----------------
__global__ __launch_bounds__(512) void k_prep(const float* __restrict__ fw,
                                              const float* __restrict__ gw,
                                              const float* __restrict__ hw) {
    int idx = blockIdx.x * 512 + threadIdx.x;   // 81920
    int row = idx >> 8, cc = idx & 255;
    const float* wp = row < 32 ? fw + row * 256
                     : row < 64 ? gw + (row - 32) * 256
                                : hw + (row - 64) * 256;
    __half h, l;
    split2h(wp[cc], h, l);
    d_wh[idx] = h;
    d_wl[idx] = l;
}

// ---------------- merged projections via 3-term fp16 HMMA, W tiles via cp.async ----------------
// grid (32 nb, 8 b), 512 threads, dyn smem 71680
__global__ __launch_bounds__(512, 1) void k_proj(
    const float* __restrict__ x,
    const float* __restrict__ fb, const float* __restrict__ gb, const float* __restrict__ hb) {
    extern __shared__ char sm[];
    const int WH = 0, WL = 25600, XH = 51200, XL = 61440;
    uint32_t sb = smem_u32(sm);
    int tid = threadIdx.x, lane = tid & 31, w = tid >> 5;
    int nb = blockIdx.x, b = blockIdx.y;
    int wm = w & 3, wn = w >> 2;
    float ap[5][4][4] = {};

    for (int c0 = 0; c0 < 256; c0 += 32) {
        __syncthreads();
        for (int t = tid; t < 1280; t += 512) {
            int row = t >> 2, p = t & 3;
            cp16(sb + WH + row * 80 + p * 16, (const char*)d_wh + (row * 256 + c0 + p * 8) * 2);
            cp16(sb + WL + row * 80 + p * 16, (const char*)d_wl + (row * 256 + c0 + p * 8) * 2);
        }
        CP_COMMIT();
        for (int idx = tid; idx < 4096; idx += 512) {
            int cc = idx >> 7, n = idx & 127;
            __half h, l;
            split2h(x[((size_t)b * 256 + c0 + cc) * 4096 + nb * 128 + n], h, l);
            *(__half*)(sm + XH + n * 80 + cc * 2) = h;
            *(__half*)(sm + XL + n * 80 + cc * 2) = l;
        }
        CP_WAIT0();
        __syncthreads();
#pragma unroll
        for (int term = 0; term < 3; term++) {
            int Ab = term == 2 ? WL : WH;
            int Bb = term == 1 ? XL : XH;
#pragma unroll
            for (int k16 = 0; k16 < 2; k16++) {
                uint32_t af[5][4];
#pragma unroll
                for (int mi = 0; mi < 5; mi++)
                    ldsm4(af[mi], sb + Ab + (wm * 80 + mi * 16 + (lane & 15)) * 80 + k16 * 32 + (lane >> 4) * 16);
#pragma unroll
                for (int p = 0; p < 2; p++) {
                    uint32_t bq[4];
                    ldsm4(bq, sb + Bb + (wn * 32 + p * 16 + ((lane >> 4) & 1) * 8 + (lane & 7)) * 80
                              + k16 * 32 + ((lane >> 3) & 1) * 16);
#pragma unroll
                    for (int mi = 0; mi < 5; mi++) {
                        mma_f16(ap[mi][2 * p],     af[mi], bq);
                        mma_f16(ap[mi][2 * p + 1], af[mi], bq + 2);
                    }
                }
            }
        }
    }
#pragma unroll
    for (int mi = 0; mi < 5; mi++)
#pragma unroll
        for (int p = 0; p < 4; p++)
#pragma unroll
            for (int hf = 0; hf < 2; hf++) {
                int orow = wm * 80 + mi * 16 + hf * 8 + (lane >> 2);
                int n = nb * 128 + wn * 32 + p * 8 + 2 * (lane & 3);
                float v0 = ap[mi][p][hf * 2 + 0];
                float v1 = ap[mi][p][hf * 2 + 1];
                if (orow < 64) {
                    __half* o = orow < 32 ? d_fp : d_gp;
                    int oo = orow & 31;
                    float bz = orow < 32 ? fb[oo] : gb[oo];
                    __half h, l;
                    split2h(v0 + bz, h, l);
                    o[((size_t)b * N + n) * 64 + oo] = h;
                    o[((size_t)b * N + n) * 64 + 32 + oo] = l;
                    split2h(v1 + bz, h, l);
                    o[((size_t)b * N + n + 1) * 64 + oo] = h;
                    o[((size_t)b * N + n + 1) * 64 + 32 + oo] = l;
                } else {
                    int c = orow - 64;
                    float bz = hb[c];
                    __half2 hv = __floats2half2_rn(v0 + bz, v1 + bz);
                    *(__half2*)&d_h[((size_t)b * C + c) * N + n] = hv;
                }
            }
}

// ---------------- pass 1: Z_j via HMMA, 3-term, p-outer (address-safe skew), g-frags hoisted ----------------
// grid (32 jb, 8 b), 256 threads, dyn smem 62464
__global__ __launch_bounds__(256, 1) void k_zsum() {
    extern __shared__ char sm[];
    const int SGH = 0, SGL = 10240;
    const int SFH[2] = {20480, 40960}, SFL[2] = {30720, 51200};
    const int SZ = 61440;
    uint32_t sb = smem_u32(sm);
    int tid = threadIdx.x, lane = tid & 31, w = tid >> 5;
    int jb = blockIdx.x, b = blockIdx.y;
    int wj = w & 3, wi2 = w >> 2;
    int ws = w >> 2;   // distinct per warp within an SMSP

    for (int t = tid; t < 1024; t += 256) {
        int row = t >> 3, p = t & 7;
        uint4 v = ((const uint4*)d_gp)[(size_t)(b * N + jb * 128 + row) * 8 + p];
        *(uint4*)(sm + (p < 4 ? SGH + row * 80 + p * 16 : SGL + row * 80 + (p - 4) * 16)) = v;
    }
    for (int t = tid; t < 1024; t += 256) {
        int row = t >> 3, p = t & 7;
        const char* src = (const char*)d_fp + ((size_t)(b * N + row) * 8 + p) * 16;
        cp16(sb + (p < 4 ? SFH[0] + row * 80 + p * 16 : SFL[0] + row * 80 + (p - 4) * 16), src);
    }
    CP_COMMIT();
    __syncthreads();

    uint32_t ga[2][2][2][4];
#pragma unroll
    for (int jt = 0; jt < 2; jt++)
#pragma unroll
        for (int k16 = 0; k16 < 2; k16++) {
            ldsm4(ga[jt][0][k16], sb + SGH + (wj * 32 + jt * 16 + (lane & 15)) * 80 + k16 * 32 + (lane >> 4) * 16);
            ldsm4(ga[jt][1][k16], sb + SGL + (wj * 32 + jt * 16 + (lane & 15)) * 80 + k16 * 32 + (lane >> 4) * 16);
        }

    float zacc[4] = {0.f, 0.f, 0.f, 0.f};
    for (int ibt = 0; ibt < 32; ibt++) {
        int cur = ibt & 1;
        __syncthreads();
        if (ibt < 31) {
            int nxt = 1 - cur;
            for (int t = tid; t < 1024; t += 256) {
                int row = t >> 3, p = t & 7;
                const char* src = (const char*)d_fp + ((size_t)(b * N + (ibt + 1) * 128 + row) * 8 + p) * 16;
                cp16(sb + (p < 4 ? SFH[nxt] + row * 80 + p * 16 : SFL[nxt] + row * 80 + (p - 4) * 16), src);
            }
        }
        CP_COMMIT();
        CP_WAIT1();
        __syncthreads();

#pragma unroll
        for (int pp = 0; pp < 4; pp++) {
            int p = (pp + ws) & 3;   // address-only skew (accumulators statically indexed)
            float t0[4] = {}, t1[4] = {}, t2[4] = {}, t3[4] = {};
#pragma unroll
            for (int k16 = 0; k16 < 2; k16++) {
                uint32_t baddr = (wi2 * 64 + p * 16 + ((lane >> 4) & 1) * 8 + (lane & 7)) * 80
                                 + k16 * 32 + ((lane >> 3) & 1) * 16;
                uint32_t bh[4];
                ldsm4(bh, sb + SFH[cur] + baddr);
                mma_f16(t0, ga[0][0][k16], bh); mma_f16(t1, ga[0][0][k16], bh + 2);
                mma_f16(t2, ga[1][0][k16], bh); mma_f16(t3, ga[1][0][k16], bh + 2);
                mma_f16(t0, ga[0][1][k16], bh); mma_f16(t1, ga[0][1][k16], bh + 2);
                mma_f16(t2, ga[1][1][k16], bh); mma_f16(t3, ga[1][1][k16], bh + 2);
                uint32_t bl[4];
                ldsm4(bl, sb + SFL[cur] + baddr);
                mma_f16(t0, ga[0][0][k16], bl); mma_f16(t1, ga[0][0][k16], bl + 2);
                mma_f16(t2, ga[1][0][k16], bl); mma_f16(t3, ga[1][0][k16], bl + 2);
            }
            zacc[0] += __expf(t0[0]) + __expf(t0[1]) + __expf(t1[0]) + __expf(t1[1]);
            zacc[1] += __expf(t0[2]) + __expf(t0[3]) + __expf(t1[2]) + __expf(t1[3]);
            zacc[2] += __expf(t2[0]) + __expf(t2[1]) + __expf(t3[0]) + __expf(t3[1]);
            zacc[3] += __expf(t2[2]) + __expf(t2[3]) + __expf(t3[2]) + __expf(t3[3]);
        }
    }
#pragma unroll
    for (int m = 0; m < 4; m++) {
        float v = zacc[m];
        v += __shfl_xor_sync(0xffffffffu, v, 1);
        v += __shfl_xor_sync(0xffffffffu, v, 2);
        if ((lane & 3) == 0) {
            int jloc = wj * 32 + (m >> 1) * 16 + (m & 1) * 8 + (lane >> 2);
            *(float*)(sm + SZ + (wi2 * 128 + jloc) * 4) = v;
        }
    }
    __syncthreads();
    if (tid < 128) {
        float z = *(float*)(sm + SZ + tid * 4) + *(float*)(sm + SZ + (128 + tid) * 4);
        d_rz[b * N + jb * 128 + tid] = 1.f / z;
    }
}

// ---------------- pass 2: 512 threads, 2 groups x 8 warps; S -> exp -> E(group) -> O ----------------
// grid (32 ib, 8 b), 512 threads, dyn smem 231424
__global__ __launch_bounds__(512, 1) void k_out(const float* __restrict__ x, float* __restrict__ out) {
    extern __shared__ char sm[];
    const int SFH = 0, SFL = 10240, SGH = 20480, SGL = 30720;
    const int SE = 40960;                       // E [128][272] group-local halves
    const int SHB[2] = {75776, 145408};         // 2 x H [256][272]
    const int SR = 215040;                      // rz for whole batch b: 16KB
    uint32_t sb = smem_u32(sm);
    int tid = threadIdx.x, lane = tid & 31, w = tid >> 5;
    int ib = blockIdx.x, b = blockIdx.y;
    int grp = w >> 3, wg = w & 7;
    int i0 = grp * 64 + (wg & 3) * 16;   // S phase: this warp's 16 i rows
    int jq = wg >> 2;                    // S phase: j half
    int ws = w >> 2;                     // distinct per warp within an SMSP

    // prologue: cp g(0), H(0), H(1); direct f + rz
    for (int t = tid; t < 1024; t += 512) {
        int row = t >> 3, p = t & 7;
        const char* src = (const char*)d_gp + ((size_t)(b * N + row) * 8 + p) * 16;
        cp16(sb + (p < 4 ? SGH + row * 80 + p * 16 : SGL + row * 80 + (p - 4) * 16), src);
    }
    CP_COMMIT();
    for (int t = tid; t < 4096; t += 512) {
        int row = t >> 4, u = t & 15;
        cp16(sb + SHB[0] + row * 272 + u * 16,
             (const char*)d_h + ((size_t)(b * C + row) * N + u * 8) * 2);
    }
    CP_COMMIT();
    for (int t = tid; t < 4096; t += 512) {
        int row = t >> 4, u = t & 15;
        cp16(sb + SHB[1] + row * 272 + u * 16,
             (const char*)d_h + ((size_t)(b * C + row) * N + 128 + u * 8) * 2);
    }
    CP_COMMIT();
    for (int t = tid; t < 1024; t += 512) {
        int row = t >> 3, p = t & 7;
        uint4 v = ((const uint4*)d_fp)[(size_t)(b * N + ib * 128 + row) * 8 + p];
        *(uint4*)(sm + (p < 4 ? SFH + row * 80 + p * 16 : SFL + row * 80 + (p - 4) * 16)) = v;
    }
    for (int t = tid; t < 1024; t += 512)
        ((float4*)(sm + SR))[t] = ((const float4*)(d_rz + (size_t)b * N))[t];
    __syncthreads();

    // hoist f A-frags (constant across all jb)
    uint32_t fah[2][4], fal[2][4];
#pragma unroll
    for (int k16 = 0; k16 < 2; k16++) {
        ldsm4(fah[k16], sb + SFH + (i0 + (lane & 15)) * 80 + k16 * 32 + (lane >> 4) * 16);
        ldsm4(fal[k16], sb + SFL + (i0 + (lane & 15)) * 80 + k16 * 32 + (lane >> 4) * 16);
    }

    float ao[2][8][4] = {};   // O: c = wg*32 + mi*16.., i = grp*64 + n*8..
    for (int jb = 0; jb < 32; jb++) {
        if (jb == 31) { CP_WAIT0(); } else { CP_WAIT1(); }  // tail: drain g(31) too
        __syncthreads();       // bar1: g/H visible, prev O done reading E

        // --- S (p-outer, 16i x 64j per warp, address-safe skew) with exp/pack/STS interleaved ---
        int irow = i0 + (lane >> 2);
#pragma unroll
        for (int pp = 0; pp < 4; pp++) {
            int p = (pp + ws) & 3;   // address-only skew
            float t0[4] = {}, t1[4] = {};
#pragma unroll
            for (int k16 = 0; k16 < 2; k16++) {
                uint32_t baddr = (jq * 64 + p * 16 + ((lane >> 4) & 1) * 8 + (lane & 7)) * 80
                                 + k16 * 32 + ((lane >> 3) & 1) * 16;
                uint32_t bh[4];
                ldsm4(bh, sb + SGH + baddr);
                mma_f16(t0, fah[k16], bh); mma_f16(t1, fah[k16], bh + 2);
                mma_f16(t0, fal[k16], bh); mma_f16(t1, fal[k16], bh + 2);
                uint32_t bl[4];
                ldsm4(bl, sb + SGL + baddr);
                mma_f16(t0, fah[k16], bl); mma_f16(t1, fah[k16], bl + 2);
            }
            int jc0 = jq * 64 + p * 16 + 2 * (lane & 3);
            float2 rz0 = *(float2*)(sm + SR + (jb * 128 + jc0) * 4);
            float2 rz1 = *(float2*)(sm + SR + (jb * 128 + jc0 + 8) * 4);
            __half2 h00 = __floats2half2_rn(__expf(t0[0]) * rz0.x, __expf(t0[1]) * rz0.y);
            __half2 h01 = __floats2half2_rn(__expf(t0[2]) * rz0.x, __expf(t0[3]) * rz0.y);
            __half2 h10 = __floats2half2_rn(__expf(t1[0]) * rz1.x, __expf(t1[1]) * rz1.y);
            __half2 h11 = __floats2half2_rn(__expf(t1[2]) * rz1.x, __expf(t1[3]) * rz1.y);
            *(uint32_t*)(sm + SE + irow * 272 + jc0 * 2)             = *(uint32_t*)&h00;
            *(uint32_t*)(sm + SE + (irow + 8) * 272 + jc0 * 2)       = *(uint32_t*)&h01;
            *(uint32_t*)(sm + SE + irow * 272 + (jc0 + 8) * 2)       = *(uint32_t*)&h10;
            *(uint32_t*)(sm + SE + (irow + 8) * 272 + (jc0 + 8) * 2) = *(uint32_t*)&h11;
        }
        BAR_GRP256(grp + 1);   // group-local (8 warps): our E half complete

        // --- O: A = H rows c (wg*32..+32), B = E rows i (grp*64..+64); k16 skewed (address-only) ---
        int SH = SHB[jb & 1];
#pragma unroll
        for (int kk = 0; kk < 8; kk++) {
            int k16 = (kk + 2 * ws) & 7;   // address-only skew
            uint32_t af[2][4];
#pragma unroll
            for (int mi = 0; mi < 2; mi++)
                ldsm4(af[mi], sb + SH + (wg * 32 + mi * 16 + (lane & 15)) * 272 + k16 * 32 + (lane >> 4) * 16);
#pragma unroll
            for (int p2 = 0; p2 < 4; p2++) {   // STATIC accumulator index
                uint32_t bq[4];
                ldsm4(bq, sb + SE + (grp * 64 + p2 * 16 + ((lane >> 4) & 1) * 8 + (lane & 7)) * 272
                          + k16 * 32 + ((lane >> 3) & 1) * 16);
#pragma unroll
                for (int mi = 0; mi < 2; mi++) {
                    mma_f16(ao[mi][2 * p2],     af[mi], bq);
                    mma_f16(ao[mi][2 * p2 + 1], af[mi], bq + 2);
                }
            }
        }
        __syncthreads();       // bar2: O reads of g/E/H(cur) done; buffers reusable

        if (jb < 31) {
            for (int t = tid; t < 1024; t += 512) {
                int row = t >> 3, p = t & 7;
                const char* src = (const char*)d_gp + ((size_t)(b * N + (jb + 1) * 128 + row) * 8 + p) * 16;
                cp16(sb + (p < 4 ? SGH + row * 80 + p * 16 : SGL + row * 80 + (p - 4) * 16), src);
            }
            CP_COMMIT();
        }
        if (jb < 30) {
            for (int t = tid; t < 4096; t += 512) {
                int row = t >> 4, u = t & 15;
                cp16(sb + SHB[jb & 1] + row * 272 + u * 16,
                     (const char*)d_h + ((size_t)(b * C + row) * N + (jb + 2) * 128 + u * 8) * 2);
            }
            CP_COMMIT();
        }
    }

    // epilogue: out[b][c][i] = O + x
#pragma unroll
    for (int mi = 0; mi < 2; mi++)
#pragma unroll
        for (int n = 0; n < 8; n++) {
            int c = wg * 32 + mi * 16 + (lane >> 2);
            int icol = ib * 128 + grp * 64 + n * 8 + 2 * (lane & 3);
            size_t idx = (size_t)(b * C + c) * N + icol;
            float2 xv = *(const float2*)&x[idx];
            *(float2*)&out[idx] = make_float2(ao[mi][n][0] + xv.x, ao[mi][n][1] + xv.y);
            idx += (size_t)8 * N;
            xv = *(const float2*)&x[idx];
            *(float2*)&out[idx] = make_float2(ao[mi][n][2] + xv.x, ao[mi][n][3] + xv.y);
        }
}

// ---------------- launch ----------------
extern "C" void kernel_launch(void* const* d_in, const int* in_sizes, int n_in,
                              void* d_out, int out_size) {
    const float* x  = (const float*)d_in[0];
    const float* fw = (const float*)d_in[1];
    const float* fb = (const float*)d_in[2];
    const float* gw = (const float*)d_in[3];
    const float* gb = (const float*)d_in[4];
    const float* hw = (const float*)d_in[5];
    const float* hb = (const float*)d_in[6];
    float* out = (float*)d_out;

    const int SM_P = 71680;
    const int SM_Z = 62464;
    const int SM_O = 231424;
    cudaFuncSetAttribute(k_proj, cudaFuncAttributeMaxDynamicSharedMemorySize, SM_P);
    cudaFuncSetAttribute(k_zsum, cudaFuncAttributeMaxDynamicSharedMemorySize, SM_Z);
    cudaFuncSetAttribute(k_out,  cudaFuncAttributeMaxDynamicSharedMemorySize, SM_O);

    k_prep<<<160, 512>>>(fw, gw, hw);
    k_proj<<<dim3(32, 8), 512, SM_P>>>(x, fb, gb, hb);
    k_zsum<<<dim3(32, 8), 256, SM_Z>>>();
    k_out<<<dim3(32, 8), 512, SM_O>>>(x, out);
}